// round 1
// baseline (speedup 1.0000x reference)
#include <cuda_runtime.h>

#define M_TOT   131072
#define N_EMB   1024
#define K_DIM   256
#define HW      4096
#define Z_ELEMS 33554432
#define GATHER_BLOCKS 4096

__device__ float g_t[N_EMB];
__device__ int   g_idx[M_TOT];
__device__ float g_part[GATHER_BLOCKS];

// ---------------------------------------------------------------------------
// Kernel 1: per-embedding squared norms t[n] = sum_c emb[n][c]^2
// ---------------------------------------------------------------------------
__global__ void k_embnorm(const float* __restrict__ emb) {
    int n = blockIdx.x * blockDim.x + threadIdx.x;
    if (n < N_EMB) {
        const float* e = emb + (size_t)n * K_DIM;
        float s = 0.f;
        #pragma unroll 8
        for (int c = 0; c < K_DIM; ++c) s = fmaf(e[c], e[c], s);
        g_t[n] = s;
    }
}

// ---------------------------------------------------------------------------
// Kernel 2: fused GEMM + argmin.
// Block = 128 pixels (consecutive hw within one batch image), 256 threads.
// N looped in chunks of 128 (emb rows), K=256 fully accumulated per chunk.
// d = fl(fl(s + t) - 2*p)  -- mirrors the reference's rounding exactly.
// First-minimum semantics preserved (strict <, ascending column order,
// lexicographic (val, idx) cross-thread combine).
// ---------------------------------------------------------------------------
__global__ __launch_bounds__(256, 2)
void k_argmin(const float* __restrict__ z, const float* __restrict__ emb,
              float* __restrict__ out) {
    __shared__ float Zs[16][128];
    __shared__ float Es[16][128];
    __shared__ float Ts[N_EMB];
    __shared__ float Rv[128 * 16];
    __shared__ int   Ri[128 * 16];

    const int tid = threadIdx.x;
    const int tx = tid & 15;
    const int ty = tid >> 4;
    const int m0 = blockIdx.x * 128;
    const int b  = m0 / HW;
    const int hw0 = m0 % HW;

    for (int i = tid; i < N_EMB; i += 256) Ts[i] = g_t[i];

    float minv[8];
    int   mini[8];
    float s_acc[8];
    #pragma unroll
    for (int i = 0; i < 8; ++i) { minv[i] = 3.4e38f; mini[i] = 0; s_acc[i] = 0.f; }

    const int r0 = ty * 4;        // rows r0..r0+3 and r1..r1+3 per thread
    const int r1 = 64 + ty * 4;
    const int c0 = tx * 4;        // cols c0..c0+3 and c1..c1+3 (ascending)
    const int c1 = 64 + tx * 4;

    for (int n0 = 0; n0 < N_EMB; n0 += 128) {
        float acc[8][8];
        #pragma unroll
        for (int i = 0; i < 8; ++i)
            #pragma unroll
            for (int j = 0; j < 8; ++j) acc[i][j] = 0.f;

        for (int kt = 0; kt < K_DIM; kt += 16) {
            __syncthreads();
            // Z tile: 16 channels x 128 pixels, coalesced float4 (hw contiguous)
            #pragma unroll
            for (int q = 0; q < 2; ++q) {
                int f4  = tid + q * 256;          // 0..511
                int cl  = f4 >> 5;                // 0..15  (channel within tile)
                int hwo = (f4 & 31) << 2;         // 0..124 (pixel offset, x4)
                float4 v = *reinterpret_cast<const float4*>(
                    z + (size_t)(b * K_DIM + kt + cl) * HW + hw0 + hwo);
                *reinterpret_cast<float4*>(&Zs[cl][hwo]) = v;
            }
            // E tile: 128 emb rows x 16 channels -> transposed into Es[k][n]
            #pragma unroll
            for (int q = 0; q < 2; ++q) {
                int f4 = tid + q * 256;
                int nl = f4 >> 2;                 // 0..127 (emb row within tile)
                int cp = (f4 & 3) << 2;           // 0,4,8,12
                float4 v = *reinterpret_cast<const float4*>(
                    emb + (size_t)(n0 + nl) * K_DIM + kt + cp);
                Es[cp + 0][nl] = v.x;
                Es[cp + 1][nl] = v.y;
                Es[cp + 2][nl] = v.z;
                Es[cp + 3][nl] = v.w;
            }
            __syncthreads();
            #pragma unroll
            for (int k = 0; k < 16; ++k) {
                float4 za = *reinterpret_cast<const float4*>(&Zs[k][r0]);
                float4 zb = *reinterpret_cast<const float4*>(&Zs[k][r1]);
                float4 ea = *reinterpret_cast<const float4*>(&Es[k][c0]);
                float4 eb = *reinterpret_cast<const float4*>(&Es[k][c1]);
                float zr[8] = {za.x, za.y, za.z, za.w, zb.x, zb.y, zb.z, zb.w};
                float er[8] = {ea.x, ea.y, ea.z, ea.w, eb.x, eb.y, eb.z, eb.w};
                if (n0 == 0) {                    // ||z||^2, sequential k order
                    #pragma unroll
                    for (int i = 0; i < 8; ++i)
                        s_acc[i] = fmaf(zr[i], zr[i], s_acc[i]);
                }
                #pragma unroll
                for (int i = 0; i < 8; ++i)
                    #pragma unroll
                    for (int j = 0; j < 8; ++j)
                        acc[i][j] = fmaf(zr[i], er[j], acc[i][j]);
            }
        }
        // epilogue: running argmin, columns strictly ascending
        #pragma unroll
        for (int j = 0; j < 8; ++j) {
            int lc = (j < 4) ? (c0 + j) : (c1 + (j - 4));
            int gc = n0 + lc;
            float t = Ts[gc];
            #pragma unroll
            for (int i = 0; i < 8; ++i) {
                float st = s_acc[i] + t;                 // fl(s + t)
                float d  = fmaf(-2.f, acc[i][j], st);    // fl(st - 2p)
                if (d < minv[i]) { minv[i] = d; mini[i] = gc; }
            }
        }
    }

    // cross-thread reduction: 16 tx-threads per row, lexicographic (val, idx)
    __syncthreads();
    #pragma unroll
    for (int i = 0; i < 8; ++i) {
        int lr = (i < 4) ? (r0 + i) : (r1 + (i - 4));
        Rv[lr * 16 + tx] = minv[i];
        Ri[lr * 16 + tx] = mini[i];
    }
    __syncthreads();
    if (tid < 128) {
        float bv = Rv[tid * 16];
        int   bi = Ri[tid * 16];
        #pragma unroll
        for (int t = 1; t < 16; ++t) {
            float v  = Rv[tid * 16 + t];
            int   ix = Ri[tid * 16 + t];
            if (v < bv || (v == bv && ix < bi)) { bv = v; bi = ix; }
        }
        int m = m0 + tid;
        g_idx[m] = bi;
        out[(size_t)Z_ELEMS + 1 + m] = (float)bi;   // indices as float
    }
}

// ---------------------------------------------------------------------------
// Kernel 3: gather z_q = emb[idx] into NCHW + per-block loss partial sums.
// Stages 32 emb rows in smem (coalesced reads), writes 128B-coalesced NCHW.
// ---------------------------------------------------------------------------
__global__ __launch_bounds__(256)
void k_gather(const float* __restrict__ z, const float* __restrict__ emb,
              float* __restrict__ out) {
    __shared__ float sm[32][257];   // +1 pad: conflict-free column reads
    __shared__ float red[256];
    const int tid = threadIdx.x;
    const int m0  = blockIdx.x * 32;
    const int b   = m0 / HW;
    const int hw0 = m0 % HW;

    for (int i = tid; i < 32 * 256; i += 256) {
        int r = i >> 8, c = i & 255;
        sm[r][c] = emb[(size_t)g_idx[m0 + r] * K_DIM + c];
    }
    __syncthreads();

    float part = 0.f;
    #pragma unroll 4
    for (int it = 0; it < 32; ++it) {
        int j = it * 256 + tid;     // 8192 = 256 channels x 32 pixels
        int c = j >> 5, r = j & 31;
        size_t o = (size_t)(b * K_DIM + c) * HW + hw0 + r;
        float v = sm[r][c];
        out[o] = v;
        float diff = v - z[o];
        part = fmaf(diff, diff, part);
    }

    red[tid] = part;
    __syncthreads();
    for (int s = 128; s > 0; s >>= 1) {
        if (tid < s) red[tid] += red[tid + s];
        __syncthreads();
    }
    if (tid == 0) g_part[blockIdx.x] = red[0];
}

// ---------------------------------------------------------------------------
// Kernel 4: deterministic final loss reduction (fixed order, fp64 accumulate)
// ---------------------------------------------------------------------------
__global__ void k_loss(float* __restrict__ out) {
    __shared__ double red[256];
    const int tid = threadIdx.x;
    double s = 0.0;
    for (int i = tid; i < GATHER_BLOCKS; i += 256) s += (double)g_part[i];
    red[tid] = s;
    __syncthreads();
    for (int k = 128; k > 0; k >>= 1) {
        if (tid < k) red[tid] += red[tid + k];
        __syncthreads();
    }
    if (tid == 0) out[Z_ELEMS] = (float)(red[0] / (double)Z_ELEMS);
}

// ---------------------------------------------------------------------------
extern "C" void kernel_launch(void* const* d_in, const int* in_sizes, int n_in,
                              void* d_out, int out_size) {
    const float* z;
    const float* emb;
    if (n_in >= 2 && in_sizes[0] == N_EMB * K_DIM && in_sizes[1] == Z_ELEMS) {
        emb = (const float*)d_in[0];
        z   = (const float*)d_in[1];
    } else {
        z   = (const float*)d_in[0];
        emb = (const float*)d_in[1];
    }
    float* out = (float*)d_out;

    k_embnorm<<<4, 256>>>(emb);
    k_argmin<<<M_TOT / 128, 256>>>(z, emb, out);
    k_gather<<<GATHER_BLOCKS, 256>>>(z, emb, out);
    k_loss<<<1, 256>>>(out);
}

// round 3
// speedup vs baseline: 1.0598x; 1.0598x over previous
#include <cuda_runtime.h>

#define M_TOT   131072
#define N_EMB   1024
#define K_DIM   256
#define HW      4096
#define Z_ELEMS 33554432
#define GATHER_BLOCKS 4096

__device__ float g_t[N_EMB];
__device__ int   g_idx[M_TOT];
__device__ float g_part[GATHER_BLOCKS];

typedef unsigned long long u64;

// ---------------------------------------------------------------------------
// Kernel 1: per-embedding squared norms t[n] = sum_c emb[n][c]^2
// ---------------------------------------------------------------------------
__global__ void k_embnorm(const float* __restrict__ emb) {
    int n = blockIdx.x * blockDim.x + threadIdx.x;
    if (n < N_EMB) {
        const float* e = emb + (size_t)n * K_DIM;
        float s = 0.f;
        #pragma unroll 8
        for (int c = 0; c < K_DIM; ++c) s = fmaf(e[c], e[c], s);
        g_t[n] = s;
    }
}

// ---------------------------------------------------------------------------
// Kernel 2: fused GEMM + argmin using packed fma.rn.f32x2 (Blackwell FFMA2).
// Per-lane rounding identical to scalar FFMA; per-output k-order accumulation
// chain unchanged vs round-1 kernel -> bit-identical distances and indices.
// Cross-thread argmin via width-16 shuffle butterfly (lexicographic, exact).
// Block = 128 pixels, 256 threads, 8x8 per-thread tile (as 8x4 f32x2 accs).
// ---------------------------------------------------------------------------
__global__ __launch_bounds__(256, 2)
void k_argmin(const float* __restrict__ z, const float* __restrict__ emb,
              float* __restrict__ out) {
    __shared__ __align__(16) float Zs[32][128];
    __shared__ __align__(16) float Es[32][128];
    __shared__ float Ts[N_EMB];

    const int tid = threadIdx.x;
    const int tx = tid & 15;
    const int ty = tid >> 4;
    const int m0 = blockIdx.x * 128;
    const int b  = m0 / HW;
    const int hw0 = m0 % HW;

    for (int i = tid; i < N_EMB; i += 256) Ts[i] = g_t[i];

    float minv[8];
    int   mini[8];
    float s_acc[8];
    #pragma unroll
    for (int i = 0; i < 8; ++i) { minv[i] = 3.4e38f; mini[i] = 0; s_acc[i] = 0.f; }

    const int r0 = ty * 4;        // rows r0..r0+3 and r1..r1+3 per thread
    const int r1 = 64 + ty * 4;
    const int c0 = tx * 4;        // cols c0..c0+3 and c1..c1+3 (ascending)
    const int c1 = 64 + tx * 4;

    for (int n0 = 0; n0 < N_EMB; n0 += 128) {
        u64 acc2[8][4];           // packed pairs: lane0 = even col, lane1 = odd col
        #pragma unroll
        for (int i = 0; i < 8; ++i)
            #pragma unroll
            for (int j = 0; j < 4; ++j) acc2[i][j] = 0ull;

        for (int kt = 0; kt < K_DIM; kt += 32) {
            __syncthreads();
            // Z tile: 32 channels x 128 pixels, coalesced float4 (hw contiguous)
            #pragma unroll
            for (int q = 0; q < 4; ++q) {
                int f4  = tid + q * 256;          // 0..1023
                int cl  = f4 >> 5;                // 0..31
                int hwo = (f4 & 31) << 2;         // 0..124
                float4 v = *reinterpret_cast<const float4*>(
                    z + (size_t)(b * K_DIM + kt + cl) * HW + hw0 + hwo);
                *reinterpret_cast<float4*>(&Zs[cl][hwo]) = v;
            }
            // E tile: 128 emb rows x 32 channels -> transposed into Es[k][n]
            #pragma unroll
            for (int q = 0; q < 4; ++q) {
                int f4 = tid + q * 256;
                int nl = f4 >> 3;                 // 0..127
                int cp = (f4 & 7) << 2;           // 0..28
                float4 v = *reinterpret_cast<const float4*>(
                    emb + (size_t)(n0 + nl) * K_DIM + kt + cp);
                Es[cp + 0][nl] = v.x;
                Es[cp + 1][nl] = v.y;
                Es[cp + 2][nl] = v.z;
                Es[cp + 3][nl] = v.w;
            }
            __syncthreads();
            #pragma unroll
            for (int k = 0; k < 32; ++k) {
                float4 za = *reinterpret_cast<const float4*>(&Zs[k][r0]);
                float4 zb = *reinterpret_cast<const float4*>(&Zs[k][r1]);
                // e pairs straight from smem (16B-aligned consecutive cols)
                double2 ed0 = *reinterpret_cast<const double2*>(&Es[k][c0]);
                double2 ed1 = *reinterpret_cast<const double2*>(&Es[k][c1]);
                u64 e2[4];
                e2[0] = *reinterpret_cast<u64*>(&ed0.x);
                e2[1] = *reinterpret_cast<u64*>(&ed0.y);
                e2[2] = *reinterpret_cast<u64*>(&ed1.x);
                e2[3] = *reinterpret_cast<u64*>(&ed1.y);
                float zr[8] = {za.x, za.y, za.z, za.w, zb.x, zb.y, zb.z, zb.w};
                if (n0 == 0) {                    // ||z||^2, sequential k order
                    #pragma unroll
                    for (int i = 0; i < 8; ++i)
                        s_acc[i] = fmaf(zr[i], zr[i], s_acc[i]);
                }
                u64 z2[8];
                #pragma unroll
                for (int i = 0; i < 8; ++i)
                    asm("mov.b64 %0, {%1, %1};" : "=l"(z2[i]) : "r"(__float_as_uint(zr[i])));
                #pragma unroll
                for (int i = 0; i < 8; ++i)
                    #pragma unroll
                    for (int j = 0; j < 4; ++j)
                        asm("fma.rn.f32x2 %0, %1, %2, %3;"
                            : "=l"(acc2[i][j])
                            : "l"(z2[i]), "l"(e2[j]), "l"(acc2[i][j]));
            }
        }
        // epilogue: running argmin, columns strictly ascending
        #pragma unroll
        for (int j = 0; j < 4; ++j) {
            int lc = (j < 2) ? (c0 + j * 2) : (c1 + (j - 2) * 2);
            int gc = n0 + lc;
            float t_even = Ts[gc];
            float t_odd  = Ts[gc + 1];
            #pragma unroll
            for (int i = 0; i < 8; ++i) {
                unsigned int plo, phi;
                asm("mov.b64 {%0, %1}, %2;" : "=r"(plo), "=r"(phi) : "l"(acc2[i][j]));
                float p_even = __uint_as_float(plo);
                float p_odd  = __uint_as_float(phi);
                float st0 = s_acc[i] + t_even;              // fl(s + t)
                float d0  = fmaf(-2.f, p_even, st0);        // fl(st - 2p)
                if (d0 < minv[i]) { minv[i] = d0; mini[i] = gc; }
                float st1 = s_acc[i] + t_odd;
                float d1  = fmaf(-2.f, p_odd, st1);
                if (d1 < minv[i]) { minv[i] = d1; mini[i] = gc + 1; }
            }
        }
    }

    // cross-thread reduction: width-16 butterfly over the tx lanes,
    // lexicographic (val, idx) combine -> exact first-min semantics.
    #pragma unroll
    for (int o = 1; o < 16; o <<= 1) {
        #pragma unroll
        for (int i = 0; i < 8; ++i) {
            float ov = __shfl_xor_sync(0xffffffffu, minv[i], o, 16);
            int   oi = __shfl_xor_sync(0xffffffffu, mini[i], o, 16);
            if (ov < minv[i] || (ov == minv[i] && oi < mini[i])) {
                minv[i] = ov; mini[i] = oi;
            }
        }
    }
    if (tx == 0) {
        #pragma unroll
        for (int i = 0; i < 8; ++i) {
            int lr = (i < 4) ? (r0 + i) : (r1 + (i - 4));
            int m = m0 + lr;
            g_idx[m] = mini[i];
            out[(size_t)Z_ELEMS + 1 + m] = (float)mini[i];   // indices as float
        }
    }
}

// ---------------------------------------------------------------------------
// Kernel 3: gather z_q = emb[idx] into NCHW + per-block loss partial sums.
// ---------------------------------------------------------------------------
__global__ __launch_bounds__(256)
void k_gather(const float* __restrict__ z, const float* __restrict__ emb,
              float* __restrict__ out) {
    __shared__ float sm[32][257];   // +1 pad: conflict-free column reads
    __shared__ float red[256];
    const int tid = threadIdx.x;
    const int m0  = blockIdx.x * 32;
    const int b   = m0 / HW;
    const int hw0 = m0 % HW;

    for (int i = tid; i < 32 * 256; i += 256) {
        int r = i >> 8, c = i & 255;
        sm[r][c] = emb[(size_t)g_idx[m0 + r] * K_DIM + c];
    }
    __syncthreads();

    float part = 0.f;
    #pragma unroll 4
    for (int it = 0; it < 32; ++it) {
        int j = it * 256 + tid;     // 8192 = 256 channels x 32 pixels
        int c = j >> 5, r = j & 31;
        size_t o = (size_t)(b * K_DIM + c) * HW + hw0 + r;
        float v = sm[r][c];
        out[o] = v;
        float diff = v - z[o];
        part = fmaf(diff, diff, part);
    }

    red[tid] = part;
    __syncthreads();
    for (int s = 128; s > 0; s >>= 1) {
        if (tid < s) red[tid] += red[tid + s];
        __syncthreads();
    }
    if (tid == 0) g_part[blockIdx.x] = red[0];
}

// ---------------------------------------------------------------------------
// Kernel 4: deterministic final loss reduction (fixed order, fp64 accumulate)
// ---------------------------------------------------------------------------
__global__ void k_loss(float* __restrict__ out) {
    __shared__ double red[256];
    const int tid = threadIdx.x;
    double s = 0.0;
    for (int i = tid; i < GATHER_BLOCKS; i += 256) s += (double)g_part[i];
    red[tid] = s;
    __syncthreads();
    for (int k = 128; k > 0; k >>= 1) {
        if (tid < k) red[tid] += red[tid + k];
        __syncthreads();
    }
    if (tid == 0) out[Z_ELEMS] = (float)(red[0] / (double)Z_ELEMS);
}

// ---------------------------------------------------------------------------
extern "C" void kernel_launch(void* const* d_in, const int* in_sizes, int n_in,
                              void* d_out, int out_size) {
    const float* z;
    const float* emb;
    if (n_in >= 2 && in_sizes[0] == N_EMB * K_DIM && in_sizes[1] == Z_ELEMS) {
        emb = (const float*)d_in[0];
        z   = (const float*)d_in[1];
    } else {
        z   = (const float*)d_in[0];
        emb = (const float*)d_in[1];
    }
    float* out = (float*)d_out;

    k_embnorm<<<4, 256>>>(emb);
    k_argmin<<<M_TOT / 128, 256>>>(z, emb, out);
    k_gather<<<GATHER_BLOCKS, 256>>>(z, emb, out);
    k_loss<<<1, 256>>>(out);
}

// round 5
// speedup vs baseline: 1.2674x; 1.1958x over previous
#include <cuda_runtime.h>
#include <cuda_bf16.h>
#include <cstdint>

#define M_TOT   131072
#define N_EMB   1024
#define K_DIM   256
#define HW      4096
#define Z_ELEMS 33554432
#define GATHER_BLOCKS 4096

__device__ float g_t[N_EMB];
__device__ int   g_idx[M_TOT];
__device__ float g_part[GATHER_BLOCKS];
__device__ __nv_bfloat16 g_A[(size_t)M_TOT * K_DIM];   // bf16(z), row-major [m][k]
__device__ __nv_bfloat16 g_B[(size_t)N_EMB * K_DIM];   // bf16(emb), row-major [n][k]
__device__ float g_P[(size_t)M_TOT * N_EMB];           // approx products (512 MB)

#define SW128(o) ((o) ^ (((o) >> 3) & 0x70))

__device__ __forceinline__ uint32_t smem_u32(const void* p) {
    uint32_t a;
    asm("{ .reg .u64 t; cvta.to.shared.u64 t, %1; cvt.u32.u64 %0, t; }" : "=r"(a) : "l"(p));
    return a;
}

#define LDSM_X4(r0, r1, r2, r3, addr) \
    asm volatile("ldmatrix.sync.aligned.m8n8.x4.shared.b16 {%0,%1,%2,%3}, [%4];" \
        : "=r"(r0), "=r"(r1), "=r"(r2), "=r"(r3) : "r"(addr))

#define MMA16816(d, a, b0, b1) \
    asm volatile("mma.sync.aligned.m16n8k16.row.col.f32.bf16.bf16.f32 " \
        "{%0,%1,%2,%3}, {%4,%5,%6,%7}, {%8,%9}, {%0,%1,%2,%3};" \
        : "+f"((d)[0]), "+f"((d)[1]), "+f"((d)[2]), "+f"((d)[3]) \
        : "r"((a)[0]), "r"((a)[1]), "r"((a)[2]), "r"((a)[3]), "r"(b0), "r"(b1))

// ===================== kernel 1: emb norms (sequential-k, exact) =========
__global__ void k_embnorm(const float* __restrict__ emb) {
    int n = blockIdx.x * blockDim.x + threadIdx.x;
    if (n < N_EMB) {
        const float* e = emb + (size_t)n * K_DIM;
        float s = 0.f;
        #pragma unroll 8
        for (int c = 0; c < K_DIM; ++c) s = fmaf(e[c], e[c], s);
        g_t[n] = s;
    }
}

// ===================== kernel 2: bf16-cast z (NCHW -> [m][k] rows) =======
__global__ __launch_bounds__(256) void k_splitA(const float* __restrict__ z) {
    __shared__ float zs[256][33];
    const int tid = threadIdx.x;
    const int m0 = blockIdx.x * 32, b = m0 / HW, hw0 = m0 & (HW - 1);
    for (int i = tid; i < 8192; i += 256) {
        int c = i >> 5, r = i & 31;
        zs[c][r] = z[((size_t)b * K_DIM + c) * HW + hw0 + r];
    }
    __syncthreads();
    for (int i = tid; i < 1024; i += 256) {
        int r = i >> 5, c8 = (i & 31) * 8;
        __nv_bfloat16 h[8];
        #pragma unroll
        for (int j = 0; j < 8; ++j) h[j] = __float2bfloat16_rn(zs[c8 + j][r]);
        *reinterpret_cast<uint4*>(&g_A[(size_t)(m0 + r) * K_DIM + c8]) =
            *reinterpret_cast<uint4*>(h);
    }
}

// ===================== kernel 3: bf16-cast emb ===========================
__global__ void k_splitB(const float* __restrict__ emb) {
    int n = blockIdx.x, c = threadIdx.x;
    g_B[(size_t)n * K_DIM + c] = __float2bfloat16_rn(emb[(size_t)n * K_DIM + c]);
}

// ===================== kernel 4: mma.sync GEMM  P = A . B^T ==============
// CTA tile 128x128, K=256 in 4 chunks of 64. 8 warps as 4(m) x 2(n),
// warp tile 32x64. SW128-swizzled smem, ldmatrix fragments.
__global__ __launch_bounds__(256) void k_gemm() {
    __shared__ __align__(16) unsigned char sA[16384];   // 128 rows x 64 halves
    __shared__ __align__(16) unsigned char sB[16384];
    const int tid = threadIdx.x, wid = tid >> 5, lane = tid & 31;
    const int m0 = blockIdx.x * 128, n0 = blockIdx.y * 128;
    const int mw = wid >> 1, nw = wid & 1;
    const int g = lane >> 2, t = lane & 3;
    const int li = lane & 7, ls = lane >> 3;
    const uint32_t sAu = smem_u32(sA), sBu = smem_u32(sB);

    float d[2][8][4];
    #pragma unroll
    for (int i = 0; i < 2; ++i)
        #pragma unroll
        for (int j = 0; j < 8; ++j)
            #pragma unroll
            for (int q = 0; q < 4; ++q) d[i][j][q] = 0.f;

    const unsigned char* gAb = reinterpret_cast<const unsigned char*>(g_A);
    const unsigned char* gBb = reinterpret_cast<const unsigned char*>(g_B);

    for (int kc = 0; kc < 4; ++kc) {
        __syncthreads();
        #pragma unroll
        for (int i = 0; i < 4; ++i) {
            int f = tid + i * 256;                // 0..1023
            int r = f >> 3, cb = (f & 7) * 16;    // row, byte-col in tile
            *reinterpret_cast<uint4*>(sA + SW128(r * 128 + cb)) =
                *reinterpret_cast<const uint4*>(gAb + (size_t)(m0 + r) * 512 + kc * 128 + cb);
            *reinterpret_cast<uint4*>(sB + SW128(r * 128 + cb)) =
                *reinterpret_cast<const uint4*>(gBb + (size_t)(n0 + r) * 512 + kc * 128 + cb);
        }
        __syncthreads();
        #pragma unroll
        for (int ks = 0; ks < 4; ++ks) {
            uint32_t a[2][4];
            #pragma unroll
            for (int mb = 0; mb < 2; ++mb) {
                int row = mw * 32 + mb * 16 + li + (ls & 1) * 8;
                int boff = ks * 32 + (ls >> 1) * 16;
                LDSM_X4(a[mb][0], a[mb][1], a[mb][2], a[mb][3],
                        sAu + SW128(row * 128 + boff));
            }
            #pragma unroll
            for (int nbp = 0; nbp < 4; ++nbp) {   // pairs of n8 blocks
                uint32_t bf[4];
                int row = nw * 64 + nbp * 16 + li + (ls >> 1) * 8;
                int boff = ks * 32 + (ls & 1) * 16;
                LDSM_X4(bf[0], bf[1], bf[2], bf[3],
                        sBu + SW128(row * 128 + boff));
                #pragma unroll
                for (int mb = 0; mb < 2; ++mb) {
                    MMA16816(d[mb][nbp * 2],     a[mb], bf[0], bf[1]);
                    MMA16816(d[mb][nbp * 2 + 1], a[mb], bf[2], bf[3]);
                }
            }
        }
    }
    // epilogue: write P (float2 per frag row)
    #pragma unroll
    for (int mb = 0; mb < 2; ++mb) {
        #pragma unroll
        for (int nb = 0; nb < 8; ++nb) {
            int m = m0 + mw * 32 + mb * 16 + g;
            int n = n0 + nw * 64 + nb * 8 + t * 2;
            float2 v0 = make_float2(d[mb][nb][0], d[mb][nb][1]);
            float2 v1 = make_float2(d[mb][nb][2], d[mb][nb][3]);
            *reinterpret_cast<float2*>(&g_P[(size_t)m * N_EMB + n]) = v0;
            *reinterpret_cast<float2*>(&g_P[(size_t)(m + 8) * N_EMB + n]) = v1;
        }
    }
}

// ===================== kernel 5: select + exact rescore ==================
// Warp per pixel. Window mn+2.5e-3 bounds every possible reference winner
// (|2*dP| <= 2.2e-3 worst-case). Candidates rescored with the exact fp32
// chain (sequential k, fmaf(-2,p,s+t)); lexicographic (d,n) = first-min.
__global__ __launch_bounds__(1024) void k_select(const float* __restrict__ z,
                                                 const float* __restrict__ emb,
                                                 float* __restrict__ out) {
    __shared__ float zs[256][33];
    __shared__ float Ts[N_EMB];
    __shared__ int   lists[32][24];
    const int tid = threadIdx.x, w = tid >> 5, l = tid & 31;
    const int m0 = blockIdx.x * 32, b = m0 / HW, hw0 = m0 & (HW - 1);

    for (int i = tid; i < 8192; i += 1024) {
        int c = i >> 5, r = i & 31;
        zs[c][r] = z[((size_t)b * K_DIM + c) * HW + hw0 + r];
    }
    for (int i = tid; i < N_EMB; i += 1024) Ts[i] = g_t[i];
    __syncthreads();

    const int m = m0 + w;
    const float* Pr = g_P + (size_t)m * N_EMB;
    float u[32];
    float mn = 3.4e38f;
    #pragma unroll
    for (int i = 0; i < 32; ++i) {
        int n = i * 32 + l;
        u[i] = fmaf(-2.f, Pr[n], Ts[n]);
        mn = fminf(mn, u[i]);
    }
    #pragma unroll
    for (int o = 16; o; o >>= 1) mn = fminf(mn, __shfl_xor_sync(0xffffffffu, mn, o));
    const float thr = mn + 2.5e-3f;
    int cnt = 0;
    #pragma unroll
    for (int i = 0; i < 32; ++i) {
        bool c = u[i] < thr;
        unsigned bal = __ballot_sync(0xffffffffu, c);
        if (c) {
            int off = cnt + __popc(bal & ((1u << l) - 1));
            if (off < 24) lists[w][off] = i * 32 + l;   // ascending n
        }
        cnt += __popc(bal);
    }
    __syncwarp();

    // exact sequential ||z||^2 (identical value in every lane)
    float s = 0.f;
    #pragma unroll 8
    for (int k = 0; k < 256; ++k) { float zv = zs[k][w]; s = fmaf(zv, zv, s); }

    float bv = 3.4e38f; int bi = 0x7fffffff;
    if (cnt <= 24) {
        if (l < cnt) {
            int n = lists[w][l];
            const float* e = emb + (size_t)n * K_DIM;
            float p = 0.f;
            #pragma unroll 8
            for (int k = 0; k < 256; ++k) p = fmaf(zs[k][w], e[k], p);
            bv = fmaf(-2.f, p, s + Ts[n]);
            bi = n;
        }
    } else {                                            // rare exact fallback
        for (int n = l; n < N_EMB; n += 32) {
            const float* e = emb + (size_t)n * K_DIM;
            float p = 0.f;
            #pragma unroll 8
            for (int k = 0; k < 256; ++k) p = fmaf(zs[k][w], e[k], p);
            float dd = fmaf(-2.f, p, s + Ts[n]);
            if (dd < bv || (dd == bv && n < bi)) { bv = dd; bi = n; }
        }
    }
    #pragma unroll
    for (int o = 16; o; o >>= 1) {
        float ov = __shfl_xor_sync(0xffffffffu, bv, o);
        int   oi = __shfl_xor_sync(0xffffffffu, bi, o);
        if (ov < bv || (ov == bv && oi < bi)) { bv = ov; bi = oi; }
    }
    if (l == 0) {
        g_idx[m] = bi;
        out[(size_t)Z_ELEMS + 1 + m] = (float)bi;
    }
}

// ===================== kernel 6: gather + loss partials ==================
__global__ __launch_bounds__(256) void k_gather(const float* __restrict__ z,
                                                const float* __restrict__ emb,
                                                float* __restrict__ out) {
    __shared__ float sm[32][257];
    __shared__ float red[256];
    const int tid = threadIdx.x;
    const int m0 = blockIdx.x * 32, b = m0 / HW, hw0 = m0 & (HW - 1);

    for (int i = tid; i < 32 * 256; i += 256) {
        int r = i >> 8, c = i & 255;
        sm[r][c] = emb[(size_t)g_idx[m0 + r] * K_DIM + c];
    }
    __syncthreads();
    float part = 0.f;
    #pragma unroll 4
    for (int it = 0; it < 32; ++it) {
        int j = it * 256 + tid;
        int c = j >> 5, r = j & 31;
        size_t o = (size_t)(b * K_DIM + c) * HW + hw0 + r;
        float v = sm[r][c];
        out[o] = v;
        float diff = v - z[o];
        part = fmaf(diff, diff, part);
    }
    red[tid] = part;
    __syncthreads();
    for (int s = 128; s > 0; s >>= 1) {
        if (tid < s) red[tid] += red[tid + s];
        __syncthreads();
    }
    if (tid == 0) g_part[blockIdx.x] = red[0];
}

// ===================== kernel 7: final loss ==============================
__global__ void k_loss(float* __restrict__ out) {
    __shared__ double red[256];
    const int tid = threadIdx.x;
    double s = 0.0;
    for (int i = tid; i < GATHER_BLOCKS; i += 256) s += (double)g_part[i];
    red[tid] = s;
    __syncthreads();
    for (int k = 128; k > 0; k >>= 1) {
        if (tid < k) red[tid] += red[tid + k];
        __syncthreads();
    }
    if (tid == 0) out[Z_ELEMS] = (float)(red[0] / (double)Z_ELEMS);
}

// =========================================================================
extern "C" void kernel_launch(void* const* d_in, const int* in_sizes, int n_in,
                              void* d_out, int out_size) {
    const float* z;
    const float* emb;
    if (n_in >= 2 && in_sizes[0] == N_EMB * K_DIM && in_sizes[1] == Z_ELEMS) {
        emb = (const float*)d_in[0];
        z   = (const float*)d_in[1];
    } else {
        z   = (const float*)d_in[0];
        emb = (const float*)d_in[1];
    }
    float* out = (float*)d_out;

    k_embnorm<<<4, 256>>>(emb);
    k_splitA<<<M_TOT / 32, 256>>>(z);
    k_splitB<<<N_EMB, 256>>>(emb);
    k_gemm<<<dim3(M_TOT / 128, N_EMB / 128), 256>>>();
    k_select<<<M_TOT / 32, 1024>>>(z, emb, out);
    k_gather<<<GATHER_BLOCKS, 256>>>(z, emb, out);
    k_loss<<<1, 256>>>(out);
}

// round 6
// speedup vs baseline: 1.5439x; 1.2182x over previous
#include <cuda_runtime.h>
#include <cuda_bf16.h>
#include <cuda_fp16.h>
#include <cstdint>

#define M_TOT   131072
#define N_EMB   1024
#define K_DIM   256
#define HW      4096
#define Z_ELEMS 33554432
#define GATHER_BLOCKS 4096

__device__ float g_t[N_EMB];
__device__ int   g_idx[M_TOT];
__device__ float g_part[GATHER_BLOCKS];
__device__ __nv_bfloat16 g_A[(size_t)M_TOT * K_DIM];   // bf16(z), row-major [m][k]
__device__ __nv_bfloat16 g_B[(size_t)N_EMB * K_DIM];   // bf16(emb), row-major [n][k]
__device__ __half g_P[(size_t)M_TOT * N_EMB];          // approx products, fp16 (256 MB)

#define SW128(o) ((o) ^ (((o) >> 3) & 0x70))

__device__ __forceinline__ uint32_t smem_u32(const void* p) {
    uint32_t a;
    asm("{ .reg .u64 t; cvta.to.shared.u64 t, %1; cvt.u32.u64 %0, t; }" : "=r"(a) : "l"(p));
    return a;
}

#define LDSM_X4(r0, r1, r2, r3, addr) \
    asm volatile("ldmatrix.sync.aligned.m8n8.x4.shared.b16 {%0,%1,%2,%3}, [%4];" \
        : "=r"(r0), "=r"(r1), "=r"(r2), "=r"(r3) : "r"(addr))

#define MMA16816(d, a, b0, b1) \
    asm volatile("mma.sync.aligned.m16n8k16.row.col.f32.bf16.bf16.f32 " \
        "{%0,%1,%2,%3}, {%4,%5,%6,%7}, {%8,%9}, {%0,%1,%2,%3};" \
        : "+f"((d)[0]), "+f"((d)[1]), "+f"((d)[2]), "+f"((d)[3]) \
        : "r"((a)[0]), "r"((a)[1]), "r"((a)[2]), "r"((a)[3]), "r"(b0), "r"(b1))

#define CP_ASYNC16(dst, src) \
    asm volatile("cp.async.cg.shared.global [%0], [%1], 16;" :: "r"(dst), "l"(src))
#define CP_COMMIT() asm volatile("cp.async.commit_group;")
#define CP_WAIT0()  asm volatile("cp.async.wait_group 0;")

// ===================== kernel 1: emb norms (sequential-k, exact) =========
__global__ void k_embnorm(const float* __restrict__ emb) {
    int n = blockIdx.x * blockDim.x + threadIdx.x;
    if (n < N_EMB) {
        const float* e = emb + (size_t)n * K_DIM;
        float s = 0.f;
        #pragma unroll 8
        for (int c = 0; c < K_DIM; ++c) s = fmaf(e[c], e[c], s);
        g_t[n] = s;
    }
}

// ===================== kernel 2: bf16-cast z (NCHW -> [m][k] rows) =======
__global__ __launch_bounds__(256) void k_splitA(const float* __restrict__ z) {
    __shared__ float zs[256][33];
    const int tid = threadIdx.x;
    const int m0 = blockIdx.x * 32, b = m0 / HW, hw0 = m0 & (HW - 1);
    for (int i = tid; i < 8192; i += 256) {
        int c = i >> 5, r = i & 31;
        zs[c][r] = z[((size_t)b * K_DIM + c) * HW + hw0 + r];
    }
    __syncthreads();
    for (int i = tid; i < 1024; i += 256) {
        int r = i >> 5, c8 = (i & 31) * 8;
        __nv_bfloat16 h[8];
        #pragma unroll
        for (int j = 0; j < 8; ++j) h[j] = __float2bfloat16_rn(zs[c8 + j][r]);
        *reinterpret_cast<uint4*>(&g_A[(size_t)(m0 + r) * K_DIM + c8]) =
            *reinterpret_cast<uint4*>(h);
    }
}

// ===================== kernel 3: bf16-cast emb ===========================
__global__ void k_splitB(const float* __restrict__ emb) {
    int n = blockIdx.x, c = threadIdx.x;
    g_B[(size_t)n * K_DIM + c] = __float2bfloat16_rn(emb[(size_t)n * K_DIM + c]);
}

// ===================== kernel 4: mma.sync GEMM  P = A . B^T ==============
// CTA tile 128x128, K=256 in 4 chunks of 64, double-buffered cp.async.
// 8 warps as 4(m) x 2(n), warp tile 32x64. SW128 smem, ldmatrix frags.
__global__ __launch_bounds__(256) void k_gemm() {
    extern __shared__ __align__(16) unsigned char smem[];
    // layout: A0 @0, A1 @16K, B0 @32K, B1 @48K (each 16KB)
    const int tid = threadIdx.x, wid = tid >> 5, lane = tid & 31;
    const int m0 = blockIdx.x * 128, n0 = blockIdx.y * 128;
    const int mw = wid >> 1, nw = wid & 1;
    const int g = lane >> 2, t = lane & 3;
    const int li = lane & 7, ls = lane >> 3;
    const uint32_t sbase = smem_u32(smem);

    const unsigned char* gAb = reinterpret_cast<const unsigned char*>(g_A);
    const unsigned char* gBb = reinterpret_cast<const unsigned char*>(g_B);

    const int r  = tid >> 3;             // 0..31 row group base (x4 iters)
    const int cb = (tid & 7) * 16;       // byte col in 128B row

    // prefetch chunk 0 into buffer 0
    {
        #pragma unroll
        for (int i = 0; i < 4; ++i) {
            int rr = r + i * 32;
            CP_ASYNC16(sbase + SW128(rr * 128 + cb),
                       gAb + (size_t)(m0 + rr) * 512 + cb);
            CP_ASYNC16(sbase + 32768u + SW128(rr * 128 + cb),
                       gBb + (size_t)(n0 + rr) * 512 + cb);
        }
        CP_COMMIT();
    }

    float d[2][8][4];
    #pragma unroll
    for (int i = 0; i < 2; ++i)
        #pragma unroll
        for (int j = 0; j < 8; ++j)
            #pragma unroll
            for (int q = 0; q < 4; ++q) d[i][j][q] = 0.f;

    uint32_t buf = 0;
    for (int kc = 0; kc < 4; ++kc) {
        CP_WAIT0();
        __syncthreads();
        // prefetch next chunk into the other buffer
        if (kc < 3) {
            uint32_t nb = buf ^ 1;
            #pragma unroll
            for (int i = 0; i < 4; ++i) {
                int rr = r + i * 32;
                CP_ASYNC16(sbase + nb * 16384u + SW128(rr * 128 + cb),
                           gAb + (size_t)(m0 + rr) * 512 + (kc + 1) * 128 + cb);
                CP_ASYNC16(sbase + 32768u + nb * 16384u + SW128(rr * 128 + cb),
                           gBb + (size_t)(n0 + rr) * 512 + (kc + 1) * 128 + cb);
            }
            CP_COMMIT();
        }
        const uint32_t sAu = sbase + buf * 16384u;
        const uint32_t sBu = sbase + 32768u + buf * 16384u;
        #pragma unroll
        for (int ks = 0; ks < 4; ++ks) {
            uint32_t a[2][4];
            #pragma unroll
            for (int mb = 0; mb < 2; ++mb) {
                int row = mw * 32 + mb * 16 + li + (ls & 1) * 8;
                int boff = ks * 32 + (ls >> 1) * 16;
                LDSM_X4(a[mb][0], a[mb][1], a[mb][2], a[mb][3],
                        sAu + SW128(row * 128 + boff));
            }
            #pragma unroll
            for (int nbp = 0; nbp < 4; ++nbp) {
                uint32_t bf[4];
                int row = nw * 64 + nbp * 16 + li + (ls >> 1) * 8;
                int boff = ks * 32 + (ls & 1) * 16;
                LDSM_X4(bf[0], bf[1], bf[2], bf[3],
                        sBu + SW128(row * 128 + boff));
                #pragma unroll
                for (int mb = 0; mb < 2; ++mb) {
                    MMA16816(d[mb][nbp * 2],     a[mb], bf[0], bf[1]);
                    MMA16816(d[mb][nbp * 2 + 1], a[mb], bf[2], bf[3]);
                }
            }
        }
        if (kc < 3) __syncthreads();   // protect buf we just computed from?? no: protect next-write target reuse
        buf ^= 1;
    }

    // epilogue: write P as fp16 (half2 per fragment pair)
    #pragma unroll
    for (int mb = 0; mb < 2; ++mb) {
        #pragma unroll
        for (int nb = 0; nb < 8; ++nb) {
            int m = m0 + mw * 32 + mb * 16 + g;
            int n = n0 + nw * 64 + nb * 8 + t * 2;
            __half2 v0 = __floats2half2_rn(d[mb][nb][0], d[mb][nb][1]);
            __half2 v1 = __floats2half2_rn(d[mb][nb][2], d[mb][nb][3]);
            *reinterpret_cast<__half2*>(&g_P[(size_t)m * N_EMB + n]) = v0;
            *reinterpret_cast<__half2*>(&g_P[(size_t)(m + 8) * N_EMB + n]) = v1;
        }
    }
}

// ===================== kernel 5: select + exact rescore ==================
// Warp per pixel. Window mn+2.5e-3 bounds every possible reference winner
// (bf16 GEMM err + fp16 store err << window). Candidates rescored with the
// exact fp32 chain; lexicographic (d,n) reduce = first-min semantics.
__global__ __launch_bounds__(1024) void k_select(const float* __restrict__ z,
                                                 const float* __restrict__ emb,
                                                 float* __restrict__ out) {
    __shared__ float zs[256][33];
    __shared__ float Ts[N_EMB];
    __shared__ int   lists[32][24];
    const int tid = threadIdx.x, w = tid >> 5, l = tid & 31;
    const int m0 = blockIdx.x * 32, b = m0 / HW, hw0 = m0 & (HW - 1);

    for (int i = tid; i < 8192; i += 1024) {
        int c = i >> 5, r = i & 31;
        zs[c][r] = z[((size_t)b * K_DIM + c) * HW + hw0 + r];
    }
    for (int i = tid; i < N_EMB; i += 1024) Ts[i] = g_t[i];
    __syncthreads();

    const int m = m0 + w;
    const __half2* Pr2 = reinterpret_cast<const __half2*>(g_P + (size_t)m * N_EMB);
    float u[32];
    float mn = 3.4e38f;
    #pragma unroll
    for (int p = 0; p < 16; ++p) {          // n = p*64 + 2l + {0,1}, coalesced
        int n = p * 64 + 2 * l;
        float2 pv = __half22float2(Pr2[p * 32 + l]);
        u[2 * p]     = fmaf(-2.f, pv.x, Ts[n]);
        u[2 * p + 1] = fmaf(-2.f, pv.y, Ts[n + 1]);
        mn = fminf(mn, fminf(u[2 * p], u[2 * p + 1]));
    }
    #pragma unroll
    for (int o = 16; o; o >>= 1) mn = fminf(mn, __shfl_xor_sync(0xffffffffu, mn, o));
    const float thr = mn + 2.5e-3f;
    int cnt = 0;
    #pragma unroll
    for (int i = 0; i < 32; ++i) {          // n = (i>>1)*64 + 2l + (i&1)
        bool c = u[i] < thr;
        unsigned bal = __ballot_sync(0xffffffffu, c);
        if (c) {
            int off = cnt + __popc(bal & ((1u << l) - 1));
            if (off < 24) lists[w][off] = (i >> 1) * 64 + 2 * l + (i & 1);
        }
        cnt += __popc(bal);
    }
    __syncwarp();

    // exact sequential ||z||^2 (identical in every lane)
    float s = 0.f;
    #pragma unroll 8
    for (int k = 0; k < 256; ++k) { float zv = zs[k][w]; s = fmaf(zv, zv, s); }

    float bv = 3.4e38f; int bi = 0x7fffffff;
    if (cnt <= 24) {
        if (l < cnt) {
            int n = lists[w][l];
            const float* e = emb + (size_t)n * K_DIM;
            float p = 0.f;
            #pragma unroll 8
            for (int k = 0; k < 256; ++k) p = fmaf(zs[k][w], e[k], p);
            bv = fmaf(-2.f, p, s + Ts[n]);
            bi = n;
        }
    } else {                                // rare exact fallback
        for (int n = l; n < N_EMB; n += 32) {
            const float* e = emb + (size_t)n * K_DIM;
            float p = 0.f;
            #pragma unroll 8
            for (int k = 0; k < 256; ++k) p = fmaf(zs[k][w], e[k], p);
            float dd = fmaf(-2.f, p, s + Ts[n]);
            if (dd < bv || (dd == bv && n < bi)) { bv = dd; bi = n; }
        }
    }
    #pragma unroll
    for (int o = 16; o; o >>= 1) {
        float ov = __shfl_xor_sync(0xffffffffu, bv, o);
        int   oi = __shfl_xor_sync(0xffffffffu, bi, o);
        if (ov < bv || (ov == bv && oi < bi)) { bv = ov; bi = oi; }
    }
    if (l == 0) {
        g_idx[m] = bi;
        out[(size_t)Z_ELEMS + 1 + m] = (float)bi;
    }
}

// ===================== kernel 6: gather + loss partials ==================
__global__ __launch_bounds__(256) void k_gather(const float* __restrict__ z,
                                                const float* __restrict__ emb,
                                                float* __restrict__ out) {
    __shared__ float sm[32][257];
    __shared__ float red[256];
    const int tid = threadIdx.x;
    const int m0 = blockIdx.x * 32, b = m0 / HW, hw0 = m0 & (HW - 1);

    for (int i = tid; i < 32 * 256; i += 256) {
        int r = i >> 8, c = i & 255;
        sm[r][c] = emb[(size_t)g_idx[m0 + r] * K_DIM + c];
    }
    __syncthreads();
    float part = 0.f;
    #pragma unroll 4
    for (int it = 0; it < 32; ++it) {
        int j = it * 256 + tid;
        int c = j >> 5, r = j & 31;
        size_t o = (size_t)(b * K_DIM + c) * HW + hw0 + r;
        float v = sm[r][c];
        out[o] = v;
        float diff = v - z[o];
        part = fmaf(diff, diff, part);
    }
    red[tid] = part;
    __syncthreads();
    for (int s = 128; s > 0; s >>= 1) {
        if (tid < s) red[tid] += red[tid + s];
        __syncthreads();
    }
    if (tid == 0) g_part[blockIdx.x] = red[0];
}

// ===================== kernel 7: final loss ==============================
__global__ void k_loss(float* __restrict__ out) {
    __shared__ double red[256];
    const int tid = threadIdx.x;
    double s = 0.0;
    for (int i = tid; i < GATHER_BLOCKS; i += 256) s += (double)g_part[i];
    red[tid] = s;
    __syncthreads();
    for (int k = 128; k > 0; k >>= 1) {
        if (tid < k) red[tid] += red[tid + k];
        __syncthreads();
    }
    if (tid == 0) out[Z_ELEMS] = (float)(red[0] / (double)Z_ELEMS);
}

// =========================================================================
extern "C" void kernel_launch(void* const* d_in, const int* in_sizes, int n_in,
                              void* d_out, int out_size) {
    const float* z;
    const float* emb;
    if (n_in >= 2 && in_sizes[0] == N_EMB * K_DIM && in_sizes[1] == Z_ELEMS) {
        emb = (const float*)d_in[0];
        z   = (const float*)d_in[1];
    } else {
        z   = (const float*)d_in[0];
        emb = (const float*)d_in[1];
    }
    float* out = (float*)d_out;

    static bool attr_set = false;
    if (!attr_set) {
        cudaFuncSetAttribute(k_gemm, cudaFuncAttributeMaxDynamicSharedMemorySize, 65536);
        attr_set = true;
    }

    k_embnorm<<<4, 256>>>(emb);
    k_splitA<<<M_TOT / 32, 256>>>(z);
    k_splitB<<<N_EMB, 256>>>(emb);
    k_gemm<<<dim3(M_TOT / 128, N_EMB / 128), 256, 65536>>>();
    k_select<<<M_TOT / 32, 1024>>>(z, emb, out);
    k_gather<<<GATHER_BLOCKS, 256>>>(z, emb, out);
    k_loss<<<1, 256>>>(out);
}

// round 7
// speedup vs baseline: 1.8184x; 1.1778x over previous
#include <cuda_runtime.h>
#include <cuda_bf16.h>
#include <cuda_fp16.h>
#include <cstdint>

#define M_TOT   131072
#define N_EMB   1024
#define K_DIM   256
#define HW      4096
#define Z_ELEMS 33554432
#define GATHER_BLOCKS 4096

__device__ float g_t[N_EMB];
__device__ float g_s[M_TOT];
__device__ int   g_idx[M_TOT];
__device__ float g_part[GATHER_BLOCKS];
__device__ __nv_bfloat16 g_A[(size_t)M_TOT * K_DIM];   // bf16(z), row-major [m][k]
__device__ __nv_bfloat16 g_B[(size_t)N_EMB * K_DIM];   // bf16(emb), row-major [n][k]
__device__ __half g_P[(size_t)M_TOT * N_EMB];          // approx products, fp16 (256 MB)

#define SW128(o) ((o) ^ (((o) >> 3) & 0x70))

__device__ __forceinline__ uint32_t smem_u32(const void* p) {
    uint32_t a;
    asm("{ .reg .u64 t; cvta.to.shared.u64 t, %1; cvt.u32.u64 %0, t; }" : "=r"(a) : "l"(p));
    return a;
}

#define LDSM_X4(r0, r1, r2, r3, addr) \
    asm volatile("ldmatrix.sync.aligned.m8n8.x4.shared.b16 {%0,%1,%2,%3}, [%4];" \
        : "=r"(r0), "=r"(r1), "=r"(r2), "=r"(r3) : "r"(addr))

#define MMA16816(d, a, b0, b1) \
    asm volatile("mma.sync.aligned.m16n8k16.row.col.f32.bf16.bf16.f32 " \
        "{%0,%1,%2,%3}, {%4,%5,%6,%7}, {%8,%9}, {%0,%1,%2,%3};" \
        : "+f"((d)[0]), "+f"((d)[1]), "+f"((d)[2]), "+f"((d)[3]) \
        : "r"((a)[0]), "r"((a)[1]), "r"((a)[2]), "r"((a)[3]), "r"(b0), "r"(b1))

#define CP_ASYNC16(dst, src) \
    asm volatile("cp.async.cg.shared.global [%0], [%1], 16;" :: "r"(dst), "l"(src))
#define CP_COMMIT() asm volatile("cp.async.commit_group;")
#define CP_WAIT0()  asm volatile("cp.async.wait_group 0;")

// ===================== kernel 1: emb norms (sequential-k, exact) =========
__global__ void k_embnorm(const float* __restrict__ emb) {
    int n = blockIdx.x * blockDim.x + threadIdx.x;
    if (n < N_EMB) {
        const float* e = emb + (size_t)n * K_DIM;
        float s = 0.f;
        #pragma unroll 8
        for (int c = 0; c < K_DIM; ++c) s = fmaf(e[c], e[c], s);
        g_t[n] = s;
    }
}

// ===================== kernel 2: bf16-cast z + exact ||z||^2 =============
__global__ __launch_bounds__(256) void k_splitA(const float* __restrict__ z) {
    __shared__ float zs[256][33];
    const int tid = threadIdx.x;
    const int m0 = blockIdx.x * 32, b = m0 / HW, hw0 = m0 & (HW - 1);
    for (int i = tid; i < 8192; i += 256) {
        int c = i >> 5, r = i & 31;
        zs[c][r] = z[((size_t)b * K_DIM + c) * HW + hw0 + r];
    }
    __syncthreads();
    for (int i = tid; i < 1024; i += 256) {
        int r = i >> 5, c8 = (i & 31) * 8;
        __nv_bfloat16 h[8];
        #pragma unroll
        for (int j = 0; j < 8; ++j) h[j] = __float2bfloat16_rn(zs[c8 + j][r]);
        *reinterpret_cast<uint4*>(&g_A[(size_t)(m0 + r) * K_DIM + c8]) =
            *reinterpret_cast<uint4*>(h);
    }
    if (tid < 32) {                      // exact sequential-k ||z||^2
        float s = 0.f;
        #pragma unroll 8
        for (int c = 0; c < K_DIM; ++c) { float v = zs[c][tid]; s = fmaf(v, v, s); }
        g_s[m0 + tid] = s;
    }
}

// ===================== kernel 3: bf16-cast emb ===========================
__global__ void k_splitB(const float* __restrict__ emb) {
    int n = blockIdx.x, c = threadIdx.x;
    g_B[(size_t)n * K_DIM + c] = __float2bfloat16_rn(emb[(size_t)n * K_DIM + c]);
}

// ===================== kernel 4: mma.sync GEMM  P = A . B^T ==============
__global__ __launch_bounds__(256) void k_gemm() {
    extern __shared__ __align__(16) unsigned char smem[];
    const int tid = threadIdx.x, wid = tid >> 5, lane = tid & 31;
    const int m0 = blockIdx.x * 128, n0 = blockIdx.y * 128;
    const int mw = wid >> 1, nw = wid & 1;
    const int g = lane >> 2, t = lane & 3;
    const int li = lane & 7, ls = lane >> 3;
    const uint32_t sbase = smem_u32(smem);

    const unsigned char* gAb = reinterpret_cast<const unsigned char*>(g_A);
    const unsigned char* gBb = reinterpret_cast<const unsigned char*>(g_B);

    const int r  = tid >> 3;
    const int cb = (tid & 7) * 16;

    {
        #pragma unroll
        for (int i = 0; i < 4; ++i) {
            int rr = r + i * 32;
            CP_ASYNC16(sbase + SW128(rr * 128 + cb),
                       gAb + (size_t)(m0 + rr) * 512 + cb);
            CP_ASYNC16(sbase + 32768u + SW128(rr * 128 + cb),
                       gBb + (size_t)(n0 + rr) * 512 + cb);
        }
        CP_COMMIT();
    }

    float d[2][8][4];
    #pragma unroll
    for (int i = 0; i < 2; ++i)
        #pragma unroll
        for (int j = 0; j < 8; ++j)
            #pragma unroll
            for (int q = 0; q < 4; ++q) d[i][j][q] = 0.f;

    uint32_t buf = 0;
    for (int kc = 0; kc < 4; ++kc) {
        CP_WAIT0();
        __syncthreads();
        if (kc < 3) {
            uint32_t nb = buf ^ 1;
            #pragma unroll
            for (int i = 0; i < 4; ++i) {
                int rr = r + i * 32;
                CP_ASYNC16(sbase + nb * 16384u + SW128(rr * 128 + cb),
                           gAb + (size_t)(m0 + rr) * 512 + (kc + 1) * 128 + cb);
                CP_ASYNC16(sbase + 32768u + nb * 16384u + SW128(rr * 128 + cb),
                           gBb + (size_t)(n0 + rr) * 512 + (kc + 1) * 128 + cb);
            }
            CP_COMMIT();
        }
        const uint32_t sAu = sbase + buf * 16384u;
        const uint32_t sBu = sbase + 32768u + buf * 16384u;
        #pragma unroll
        for (int ks = 0; ks < 4; ++ks) {
            uint32_t a[2][4];
            #pragma unroll
            for (int mb = 0; mb < 2; ++mb) {
                int row = mw * 32 + mb * 16 + li + (ls & 1) * 8;
                int boff = ks * 32 + (ls >> 1) * 16;
                LDSM_X4(a[mb][0], a[mb][1], a[mb][2], a[mb][3],
                        sAu + SW128(row * 128 + boff));
            }
            #pragma unroll
            for (int nbp = 0; nbp < 4; ++nbp) {
                uint32_t bf[4];
                int row = nw * 64 + nbp * 16 + li + (ls >> 1) * 8;
                int boff = ks * 32 + (ls & 1) * 16;
                LDSM_X4(bf[0], bf[1], bf[2], bf[3],
                        sBu + SW128(row * 128 + boff));
                #pragma unroll
                for (int mb = 0; mb < 2; ++mb) {
                    MMA16816(d[mb][nbp * 2],     a[mb], bf[0], bf[1]);
                    MMA16816(d[mb][nbp * 2 + 1], a[mb], bf[2], bf[3]);
                }
            }
        }
        if (kc < 3) __syncthreads();
        buf ^= 1;
    }

    #pragma unroll
    for (int mb = 0; mb < 2; ++mb) {
        #pragma unroll
        for (int nb = 0; nb < 8; ++nb) {
            int m = m0 + mw * 32 + mb * 16 + g;
            int n = n0 + nw * 64 + nb * 8 + t * 2;
            __half2 v0 = __floats2half2_rn(d[mb][nb][0], d[mb][nb][1]);
            __half2 v1 = __floats2half2_rn(d[mb][nb][2], d[mb][nb][3]);
            *reinterpret_cast<__half2*>(&g_P[(size_t)m * N_EMB + n]) = v0;
            *reinterpret_cast<__half2*>(&g_P[(size_t)(m + 8) * N_EMB + n]) = v1;
        }
    }
}

// ===================== kernel 5: select + rescore + gather + loss ========
// 256 threads, 8 warps x 4-pixel loop = 32 pixels/block. P row kept packed
// in 16 half2 regs/lane (no u[] array -> no spills). After indices known,
// gather winning emb rows and write z_q + loss partial reusing staged zs.
__global__ __launch_bounds__(256) void k_select(const float* __restrict__ z,
                                                const float* __restrict__ emb,
                                                float* __restrict__ out) {
    extern __shared__ __align__(16) unsigned char dsm[];
    float (*zs)[33]   = reinterpret_cast<float(*)[33]>(dsm);            // 33792 B
    float* Ts         = reinterpret_cast<float*>(dsm + 33792);          // 4096 B
    float (*sm)[257]  = reinterpret_cast<float(*)[257]>(dsm + 37888);   // 32896 B
    int  (*lists)[24] = reinterpret_cast<int(*)[24]>(dsm + 70784);      // 768 B
    int*  sidx        = reinterpret_cast<int*>(dsm + 71552);            // 128 B

    const int tid = threadIdx.x, w = tid >> 5, l = tid & 31;
    const int m0 = blockIdx.x * 32, b = m0 / HW, hw0 = m0 & (HW - 1);

    for (int i = tid; i < 8192; i += 256) {
        int c = i >> 5, r = i & 31;
        zs[c][r] = z[((size_t)b * K_DIM + c) * HW + hw0 + r];
    }
    for (int i = tid; i < N_EMB; i += 256) Ts[i] = g_t[i];
    __syncthreads();

    for (int sub = 0; sub < 4; ++sub) {
        const int px = w * 4 + sub;            // pixel within block
        const int m = m0 + px;
        const __half2* Pr2 = reinterpret_cast<const __half2*>(g_P + (size_t)m * N_EMB);

        uint32_t pr[16];
        #pragma unroll
        for (int j = 0; j < 16; ++j)
            pr[j] = reinterpret_cast<const uint32_t*>(Pr2)[j * 32 + l];

        float mn = 3.4e38f;
        #pragma unroll
        for (int j = 0; j < 16; ++j) {         // n = j*64 + 2l + {0,1}
            int n = j * 64 + 2 * l;
            float2 pv = __half22float2(*reinterpret_cast<__half2*>(&pr[j]));
            float u0 = fmaf(-2.f, pv.x, Ts[n]);
            float u1 = fmaf(-2.f, pv.y, Ts[n + 1]);
            mn = fminf(mn, fminf(u0, u1));
        }
        #pragma unroll
        for (int o = 16; o; o >>= 1) mn = fminf(mn, __shfl_xor_sync(0xffffffffu, mn, o));
        const float thr = mn + 2.5e-3f;

        int cnt = 0;
        #pragma unroll
        for (int j = 0; j < 16; ++j) {
            int n = j * 64 + 2 * l;
            float2 pv = __half22float2(*reinterpret_cast<__half2*>(&pr[j]));
            float u0 = fmaf(-2.f, pv.x, Ts[n]);
            float u1 = fmaf(-2.f, pv.y, Ts[n + 1]);
            bool c0 = u0 < thr, c1 = u1 < thr;
            unsigned b0 = __ballot_sync(0xffffffffu, c0);
            if (c0) {
                int off = cnt + __popc(b0 & ((1u << l) - 1));
                if (off < 24) lists[w][off] = n;
            }
            cnt += __popc(b0);
            unsigned b1 = __ballot_sync(0xffffffffu, c1);
            if (c1) {
                int off = cnt + __popc(b1 & ((1u << l) - 1));
                if (off < 24) lists[w][off] = n + 1;
            }
            cnt += __popc(b1);
        }
        __syncwarp();

        const float s = g_s[m];                // exact sequential ||z||^2
        float bv = 3.4e38f; int bi = 0x7fffffff;
        if (cnt <= 24) {
            if (l < cnt) {
                int n = lists[w][l];
                const float* e = emb + (size_t)n * K_DIM;
                float p = 0.f;
                #pragma unroll 8
                for (int k = 0; k < 256; ++k) p = fmaf(zs[k][px], e[k], p);
                bv = fmaf(-2.f, p, s + Ts[n]);
                bi = n;
            }
        } else {                               // rare exact fallback
            for (int n = l; n < N_EMB; n += 32) {
                const float* e = emb + (size_t)n * K_DIM;
                float p = 0.f;
                #pragma unroll 8
                for (int k = 0; k < 256; ++k) p = fmaf(zs[k][px], e[k], p);
                float dd = fmaf(-2.f, p, s + Ts[n]);
                if (dd < bv || (dd == bv && n < bi)) { bv = dd; bi = n; }
            }
        }
        #pragma unroll
        for (int o = 16; o; o >>= 1) {
            float ov = __shfl_xor_sync(0xffffffffu, bv, o);
            int   oi = __shfl_xor_sync(0xffffffffu, bi, o);
            if (ov < bv || (ov == bv && oi < bi)) { bv = ov; bi = oi; }
        }
        if (l == 0) {
            g_idx[m] = bi;
            sidx[px] = bi;
            out[(size_t)Z_ELEMS + 1 + m] = (float)bi;
        }
    }
    __syncthreads();

    // gather winning emb rows (coalesced) then write z_q NCHW + loss partial
    for (int i = tid; i < 32 * 256; i += 256) {
        int r = i >> 8, c = i & 255;
        sm[r][c] = emb[(size_t)sidx[r] * K_DIM + c];
    }
    __syncthreads();
    float part = 0.f;
    #pragma unroll 4
    for (int it = 0; it < 32; ++it) {
        int j = it * 256 + tid;
        int c = j >> 5, r = j & 31;
        size_t o = (size_t)(b * K_DIM + c) * HW + hw0 + r;
        float v = sm[r][c];
        out[o] = v;
        float diff = v - zs[c][r];
        part = fmaf(diff, diff, part);
    }
    float* red = Ts;                           // Ts no longer needed
    __syncthreads();
    red[tid] = part;
    __syncthreads();
    for (int st = 128; st > 0; st >>= 1) {
        if (tid < st) red[tid] += red[tid + st];
        __syncthreads();
    }
    if (tid == 0) g_part[blockIdx.x] = red[0];
}

// ===================== kernel 6: final loss ==============================
__global__ void k_loss(float* __restrict__ out) {
    __shared__ double red[256];
    const int tid = threadIdx.x;
    double s = 0.0;
    for (int i = tid; i < GATHER_BLOCKS; i += 256) s += (double)g_part[i];
    red[tid] = s;
    __syncthreads();
    for (int k = 128; k > 0; k >>= 1) {
        if (tid < k) red[tid] += red[tid + k];
        __syncthreads();
    }
    if (tid == 0) out[Z_ELEMS] = (float)(red[0] / (double)Z_ELEMS);
}

// =========================================================================
extern "C" void kernel_launch(void* const* d_in, const int* in_sizes, int n_in,
                              void* d_out, int out_size) {
    const float* z;
    const float* emb;
    if (n_in >= 2 && in_sizes[0] == N_EMB * K_DIM && in_sizes[1] == Z_ELEMS) {
        emb = (const float*)d_in[0];
        z   = (const float*)d_in[1];
    } else {
        z   = (const float*)d_in[0];
        emb = (const float*)d_in[1];
    }
    float* out = (float*)d_out;

    static bool attr_set = false;
    if (!attr_set) {
        cudaFuncSetAttribute(k_gemm, cudaFuncAttributeMaxDynamicSharedMemorySize, 65536);
        cudaFuncSetAttribute(k_select, cudaFuncAttributeMaxDynamicSharedMemorySize, 72 * 1024);
        attr_set = true;
    }

    k_embnorm<<<4, 256>>>(emb);
    k_splitA<<<M_TOT / 32, 256>>>(z);
    k_splitB<<<N_EMB, 256>>>(emb);
    k_gemm<<<dim3(M_TOT / 128, N_EMB / 128), 256, 65536>>>();
    k_select<<<M_TOT / 32, 256, 72 * 1024>>>(z, emb, out);
    k_loss<<<1, 256>>>(out);
}